// round 8
// baseline (speedup 1.0000x reference)
#include <cuda_runtime.h>
#include <cstdint>

// Problem constants (fixed by reference setup_inputs)
#define NB  8      // batch
#define CCH 512    // channels
#define NH  8      // heads
#define DD  64     // head dim
#define LL  64     // token length
#define CTK 256    // token channels
#define HW  16384  // 128*128 pixels

#define EPAD 132   // epilogue buffer row stride (floats)

// Scratch (device globals — no allocations allowed)
__device__ __align__(16) float g_k[NB * CCH * LL];  // [nh][l][d] tf32-rounded, pre-scaled 1/8
__device__ __align__(16) float g_v[NB * CCH * LL];  // [nh][d][l] tf32-rounded

__device__ __forceinline__ uint32_t f2tf32(float x) {
    uint32_t r;
    asm("cvt.rn.tf32.f32 %0, %1;" : "=r"(r) : "f"(x));
    return r;
}

// m16n8k8 tf32 HMMA (base-target instruction, works at compute_103)
__device__ __forceinline__ void mma_tf32(float* c,
                                         uint32_t a0, uint32_t a1, uint32_t a2, uint32_t a3,
                                         uint32_t b0, uint32_t b1) {
    asm volatile(
        "mma.sync.aligned.m16n8k8.row.col.f32.tf32.tf32.f32 "
        "{%0,%1,%2,%3}, {%4,%5,%6,%7}, {%8,%9}, {%0,%1,%2,%3};"
        : "+f"(c[0]), "+f"(c[1]), "+f"(c[2]), "+f"(c[3])
        : "r"(a0), "r"(a1), "r"(a2), "r"(a3), "r"(b0), "r"(b1));
}

// ============================================================================
// Kernel 1: fused V/K projections (1x1 conv, K=256).
//   g_k[nh][l][d] = K/8 (tf32-rounded)  — GEMM1 B operand (k-dim = d)
//   g_v[nh][d][l] = V   (tf32-rounded)  — GEMM2 B operand (k-dim = l)
// ============================================================================
__global__ void vk_kernel(const float* __restrict__ token,
                          const float* __restrict__ Wv, const float* __restrict__ bv,
                          const float* __restrict__ Wk, const float* __restrict__ bk) {
    __shared__ float wv_s[CTK];
    __shared__ float wk_s[CTK];
    const int o = blockIdx.x & (CCH - 1);
    const int n = blockIdx.x >> 9;
    const int l = threadIdx.x;

#pragma unroll
    for (int i = 0; i < 4; i++) {
        wv_s[l + 64 * i] = Wv[o * CTK + l + 64 * i];
        wk_s[l + 64 * i] = Wk[o * CTK + l + 64 * i];
    }
    __syncthreads();

    const float* tok = token + n * (CTK * LL) + l;
    float av0 = 0.f, av1 = 0.f, ak0 = 0.f, ak1 = 0.f;
#pragma unroll 8
    for (int ct = 0; ct < CTK; ct += 2) {
        float t0 = tok[ct * LL];
        float t1 = tok[(ct + 1) * LL];
        av0 = fmaf(wv_s[ct],     t0, av0);
        ak0 = fmaf(wk_s[ct],     t0, ak0);
        av1 = fmaf(wv_s[ct + 1], t1, av1);
        ak1 = fmaf(wk_s[ct + 1], t1, ak1);
    }
    float av = av0 + av1 + bv[o];
    float ak = (ak0 + ak1 + bk[o]) * 0.125f;  // 1/sqrt(C/h) = 1/8

    const int h = o >> 6, d = o & 63;
    const int slice = (n * NH + h) * (DD * LL);
    g_k[slice + l * DD + d] = __uint_as_float(f2tf32(ak));  // [l][d]
    g_v[slice + d * LL + l] = __uint_as_float(f2tf32(av));  // [d][l]
}

// ============================================================================
// Kernel 2: mma.sync tf32 attention, M=32 per warp, 2 pixel-tiles per CTA.
// CTA = 128 threads; processes 256 pixels of one (n,h); grid = 64 * 64 = 4096.
// Pixel permutation: MMA row r <-> local px 2*(r&7)+(r>>3), so Q fragments
// load as float2 (LDG.64, 64B per line-touch) and GEMM2 outputs pair into
// float2 epilogue stores. K/V staged once per CTA (amortized over 2 tiles).
// Smem (dynamic 66.5KB): ks 16K | vs 16K | epi 64x132 floats.
// ============================================================================
__global__ __launch_bounds__(128, 3)
void attn_kernel(const float* __restrict__ feature, float* __restrict__ out) {
    extern __shared__ __align__(16) float sm[];
    float* ks = sm;              // [64 l][64 d] packed-pair rotated
    float* vs = sm + 4096;       // [64 d][64 l] packed-pair rotated
    float* es = sm + 8192;       // [64 d][EPAD] epilogue transpose buffer

    const int tid  = threadIdx.x;
    const int lane = tid & 31;
    const int warp = tid >> 5;
    const int gid  = lane >> 2;   // fragment row group
    const int qid  = lane & 3;    // fragment col group
    const int nh   = blockIdx.x >> 6;
    const int tile2 = blockIdx.x & 63;

    // ---- stage K/V: (row, col) -> row*64 + 2*((4*(col/8)+(col&3)+4*row)&31) + ((col>>2)&1)
    // (fragment pair (col, col+4) becomes one aligned, bank-unique float2)
    {
        const float4* gk4 = reinterpret_cast<const float4*>(g_k) + nh * 1024;
        const float4* gv4 = reinterpret_cast<const float4*>(g_v) + nh * 1024;
#pragma unroll
        for (int i = 0; i < 8; i++) {
            int idx = tid + 128 * i;             // float4 index 0..1023
            int row = idx >> 4, c = idx & 15;
            int w = c & 1, ktb = 4 * (c >> 1) + 4 * row;
            float4 kv = gk4[idx];
            float4 vv = gv4[idx];
            float* kb = ks + row * 64 + w;
            float* vb = vs + row * 64 + w;
            kb[2 * ((ktb + 0) & 31)] = kv.x;  vb[2 * ((ktb + 0) & 31)] = vv.x;
            kb[2 * ((ktb + 1) & 31)] = kv.y;  vb[2 * ((ktb + 1) & 31)] = vv.y;
            kb[2 * ((ktb + 2) & 31)] = kv.z;  vb[2 * ((ktb + 2) & 31)] = vv.z;
            kb[2 * ((ktb + 3) & 31)] = kv.w;  vb[2 * ((ktb + 3) & 31)] = vv.w;
        }
    }
    __syncthreads();

    const int rot = (qid + 4 * gid) & 31;
    const float* fhead = feature + nh * (DD * HW);
    float*       ohead = out     + nh * (DD * HW);

    for (int it = 0; it < 2; it++) {
        const int pixbase = (tile2 * 2 + it) * 128;
        const float* f = fhead + pixbase + warp * 32;

        // ---- GEMM1: acc[2 m-tiles][8 n-tiles][4]; Q frags via LDG.64 (px-perm) ----
        float acc[64];
#pragma unroll
        for (int i = 0; i < 64; i++) acc[i] = 0.f;
#pragma unroll
        for (int kt = 0; kt < 8; kt++) {
            uint32_t a[2][4];
#pragma unroll
            for (int T = 0; T < 2; T++) {
                // row gid <-> px 2gid, row gid+8 <-> px 2gid+1  (within 16-px tile T)
                float2 q0 = *reinterpret_cast<const float2*>(f + (8 * kt + qid) * HW + 16 * T + 2 * gid);
                float2 q1 = *reinterpret_cast<const float2*>(f + (8 * kt + qid + 4) * HW + 16 * T + 2 * gid);
                a[T][0] = f2tf32(q0.x);   // (row gid,   col qid)
                a[T][1] = f2tf32(q0.y);   // (row gid+8, col qid)
                a[T][2] = f2tf32(q1.x);   // (row gid,   col qid+4)
                a[T][3] = f2tf32(q1.y);   // (row gid+8, col qid+4)
            }
            const int c2 = (4 * kt + rot) & 31;
#pragma unroll
            for (int j = 0; j < 8; j++) {
                float2 b = *reinterpret_cast<const float2*>(&ks[(8 * j + gid) * 64 + 2 * c2]);
                uint32_t b0 = __float_as_uint(b.x), b1 = __float_as_uint(b.y);
                mma_tf32(&acc[4 * j],      a[0][0], a[0][1], a[0][2], a[0][3], b0, b1);
                mma_tf32(&acc[32 + 4 * j], a[1][0], a[1][1], a[1][2], a[1][3], b0, b1);
            }
        }

        // ---- softmax per m-tile (rows gid via c0/c1, gid+8 via c2/c3) ----
#pragma unroll
        for (int T = 0; T < 2; T++) {
            float* ac = acc + 32 * T;
            float m0 = -1e30f, m1 = -1e30f;
#pragma unroll
            for (int j = 0; j < 8; j++) {
                m0 = fmaxf(m0, fmaxf(ac[4 * j + 0], ac[4 * j + 1]));
                m1 = fmaxf(m1, fmaxf(ac[4 * j + 2], ac[4 * j + 3]));
            }
            m0 = fmaxf(m0, __shfl_xor_sync(0xffffffffu, m0, 1));
            m0 = fmaxf(m0, __shfl_xor_sync(0xffffffffu, m0, 2));
            m1 = fmaxf(m1, __shfl_xor_sync(0xffffffffu, m1, 1));
            m1 = fmaxf(m1, __shfl_xor_sync(0xffffffffu, m1, 2));
            float s0 = 0.f, s1 = 0.f;
#pragma unroll
            for (int j = 0; j < 8; j++) {
                ac[4 * j + 0] = __expf(ac[4 * j + 0] - m0); s0 += ac[4 * j + 0];
                ac[4 * j + 1] = __expf(ac[4 * j + 1] - m0); s0 += ac[4 * j + 1];
                ac[4 * j + 2] = __expf(ac[4 * j + 2] - m1); s1 += ac[4 * j + 2];
                ac[4 * j + 3] = __expf(ac[4 * j + 3] - m1); s1 += ac[4 * j + 3];
            }
            s0 += __shfl_xor_sync(0xffffffffu, s0, 1);
            s0 += __shfl_xor_sync(0xffffffffu, s0, 2);
            s1 += __shfl_xor_sync(0xffffffffu, s1, 1);
            s1 += __shfl_xor_sync(0xffffffffu, s1, 2);
            const float inv0 = __frcp_rn(s0);
            const float inv1 = __frcp_rn(s1);
#pragma unroll
            for (int j = 0; j < 8; j++) {
                ac[4 * j + 0] = __uint_as_float(f2tf32(ac[4 * j + 0] * inv0));
                ac[4 * j + 1] = __uint_as_float(f2tf32(ac[4 * j + 1] * inv0));
                ac[4 * j + 2] = __uint_as_float(f2tf32(ac[4 * j + 2] * inv1));
                ac[4 * j + 3] = __uint_as_float(f2tf32(ac[4 * j + 3] * inv1));
            }
        }

        // ---- remap coef D-frag -> A-frag in place (row-preserving; perm-safe) ----
        {
            const int s0 = 4 * gid + (qid >> 1);
            const int s1 = s0 + 2;
            const bool odd = qid & 1;
#pragma unroll
            for (int T = 0; T < 2; T++) {
                float* ac = acc + 32 * T;
#pragma unroll
                for (int t = 0; t < 8; t++) {
                    float v0 = __shfl_sync(0xffffffffu, ac[4 * t + 0], s0);
                    float v1 = __shfl_sync(0xffffffffu, ac[4 * t + 1], s0);
                    float v2 = __shfl_sync(0xffffffffu, ac[4 * t + 2], s0);
                    float v3 = __shfl_sync(0xffffffffu, ac[4 * t + 3], s0);
                    float w0 = __shfl_sync(0xffffffffu, ac[4 * t + 0], s1);
                    float w1 = __shfl_sync(0xffffffffu, ac[4 * t + 1], s1);
                    float w2 = __shfl_sync(0xffffffffu, ac[4 * t + 2], s1);
                    float w3 = __shfl_sync(0xffffffffu, ac[4 * t + 3], s1);
                    ac[4 * t + 0] = odd ? v1 : v0;
                    ac[4 * t + 1] = odd ? v3 : v2;
                    ac[4 * t + 2] = odd ? w1 : w0;
                    ac[4 * t + 3] = odd ? w3 : w2;
                }
            }
        }

        // ---- GEMM2: pr[2][8 d-tiles][4] = coef * V^T ----
        float pr[64];
#pragma unroll
        for (int i = 0; i < 64; i++) pr[i] = 0.f;
#pragma unroll
        for (int t = 0; t < 8; t++) {
            const int c2 = (4 * t + rot) & 31;
#pragma unroll
            for (int j = 0; j < 8; j++) {
                float2 b = *reinterpret_cast<const float2*>(&vs[(8 * j + gid) * 64 + 2 * c2]);
                uint32_t b0 = __float_as_uint(b.x), b1 = __float_as_uint(b.y);
                mma_tf32(&pr[4 * j],
                         __float_as_uint(acc[4 * t + 0]), __float_as_uint(acc[4 * t + 1]),
                         __float_as_uint(acc[4 * t + 2]), __float_as_uint(acc[4 * t + 3]), b0, b1);
                mma_tf32(&pr[32 + 4 * j],
                         __float_as_uint(acc[32 + 4 * t + 0]), __float_as_uint(acc[32 + 4 * t + 1]),
                         __float_as_uint(acc[32 + 4 * t + 2]), __float_as_uint(acc[32 + 4 * t + 3]), b0, b1);
            }
        }

        // ---- epilogue: D-frags -> es via STS.64 pairs, then coalesced pass ----
        __syncthreads();   // previous iteration's epilogue reads complete
#pragma unroll
        for (int T = 0; T < 2; T++) {
#pragma unroll
            for (int j = 0; j < 8; j++) {
                int px = warp * 32 + 16 * T + 2 * gid;   // (c0,c2) = px, px+1 at same d
                int d  = 8 * j + 2 * qid;
                *reinterpret_cast<float2*>(&es[d * EPAD + px]) =
                    make_float2(pr[32 * T + 4 * j + 0], pr[32 * T + 4 * j + 2]);
                *reinterpret_cast<float2*>(&es[(d + 1) * EPAD + px]) =
                    make_float2(pr[32 * T + 4 * j + 1], pr[32 * T + 4 * j + 3]);
            }
        }
        __syncthreads();

        {
            const float* fb = fhead + pixbase;
            float*       ob = ohead + pixbase;
            const int px4 = lane * 4;
#pragma unroll
            for (int i = 0; i < 16; i++) {
                int d = warp * 16 + i;
                float4 p  = *reinterpret_cast<const float4*>(&es[d * EPAD + px4]);
                float4 fv = *reinterpret_cast<const float4*>(&fb[d * HW + px4]);
                float4 ov;
                ov.x = fv.x + p.x; ov.y = fv.y + p.y;
                ov.z = fv.z + p.z; ov.w = fv.w + p.w;
                *reinterpret_cast<float4*>(&ob[d * HW + px4]) = ov;
            }
        }
    }
}

// ============================================================================
extern "C" void kernel_launch(void* const* d_in, const int* in_sizes, int n_in,
                              void* d_out, int out_size) {
    const float* feature = (const float*)d_in[0];
    const float* token   = (const float*)d_in[1];
    const float* Wv      = (const float*)d_in[2];
    const float* bv      = (const float*)d_in[3];
    const float* Wk      = (const float*)d_in[4];
    const float* bk      = (const float*)d_in[5];
    float* out = (float*)d_out;

    const int smem_bytes = (8192 + 64 * EPAD) * 4;   // 66560 B
    cudaFuncSetAttribute(attn_kernel, cudaFuncAttributeMaxDynamicSharedMemorySize, smem_bytes);

    vk_kernel<<<NB * CCH, 64>>>(token, Wv, bv, Wk, bk);
    attn_kernel<<<NB * NH * 64, 128, smem_bytes>>>(feature, out);
}